// round 16
// baseline (speedup 1.0000x reference)
#include <cuda_runtime.h>
#include <cstdint>

// Problem constants
#define BATCH 16384
#define NN    1024
#define NI    128
#define NO    64
#define REFRACTORY 0.9f

#define KC       64
#define NCHUNK   (NN / KC)          // 16
#define MT       128                // rows per CTA
#define NTHREADS 128                // 4 warps x 32 rows, each warp all 64 cols
#define GRID     (BATCH / MT)       // 128
#define STAGES   3

// ---- dynamic smem layout ----
// ring of 3 stages: A 32KB (128 rows x 256B, swizzled) + B 16KB (packed image)
#define A_BYTES     32768
#define B_BYTES     16384
#define STAGE_BYTES (A_BYTES + B_BYTES)          // 49152
#define SMEM_TOTAL  (STAGES * STAGE_BYTES)       // 147456

// B packed image (16KB per chunk), tf32-rounded, refractory-folded:
// uint4 idx within chunk = (ks*4 + ntp)*32 + lane ; 4 floats =
//   {nt=2ntp:k, nt=2ntp:k+4, nt=2ntp+1:k, nt=2ntp+1:k+4}
//   k = chunk*64 + ks*8 + (lane&3),  n = nt*8 + (lane>>2)
__device__ __align__(16) float g_Bpack[NCHUNK * 8 * 4 * 32 * 4];

__device__ __forceinline__ uint32_t smem_u32(const void* p) {
    uint32_t a;
    asm("{ .reg .u64 t; cvta.to.shared.u64 t, %1; cvt.u32.u64 %0, t; }" : "=r"(a) : "l"(p));
    return a;
}
__device__ __forceinline__ void ldm_x4(uint32_t* r, uint32_t addr) {
    asm volatile("ldmatrix.sync.aligned.m8n8.x4.shared.b16 {%0,%1,%2,%3}, [%4];"
                 : "=r"(r[0]), "=r"(r[1]), "=r"(r[2]), "=r"(r[3]) : "r"(addr));
}
__device__ __forceinline__ void mma_tf32(float* d, const uint32_t* a, uint32_t b0, uint32_t b1) {
    asm volatile(
        "mma.sync.aligned.m16n8k8.row.col.f32.tf32.tf32.f32 "
        "{%0,%1,%2,%3}, {%4,%5,%6,%7}, {%8,%9}, {%0,%1,%2,%3};"
        : "+f"(d[0]), "+f"(d[1]), "+f"(d[2]), "+f"(d[3])
        : "r"(a[0]), "r"(a[1]), "r"(a[2]), "r"(a[3]), "r"(b0), "r"(b1));
}
__device__ __forceinline__ uint32_t cvt_tf32(uint32_t x) {
    uint32_t d;
    asm("cvt.rna.tf32.f32 %0, %1;" : "=r"(d) : "f"(__uint_as_float(x)));
    return d;
}
__device__ __forceinline__ void cp_async16(uint32_t smem_addr, const void* gptr) {
    asm volatile("cp.async.cg.shared.global [%0], [%1], 16;"
                 :: "r"(smem_addr), "l"(gptr) : "memory");
}
#define CP_COMMIT() asm volatile("cp.async.commit_group;" ::: "memory")
#define CP_WAIT1()  asm volatile("cp.async.wait_group 1;" ::: "memory")

// A stage: 128 rows x 16 units(16B); two 16KB halves (u<8 / u>=8), swizzled.
// Conflict-free for cp.async stores and ldmatrix reads.
__device__ __forceinline__ uint32_t a_off(int row, int u) {
    return (uint32_t)(((u >> 3) << 14) + (row << 7) + (((u & 7) ^ (row & 7)) << 4));
}

// ---------------- prep: round + fold + pack weight slice ----------------
__global__ void prep_kernel(const float* __restrict__ W) {
    int idx = blockIdx.x * blockDim.x + threadIdx.x;   // 0..65535
    if (idx >= NN * NO) return;
    int j     = idx & 3;
    int lane  = (idx >> 2) & 31;
    int ntp   = (idx >> 7) & 3;
    int ks    = (idx >> 9) & 7;
    int chunk = idx >> 12;
    int nt = 2 * ntp + (j >> 1);
    int k  = chunk * 64 + ks * 8 + (lane & 3) + (j & 1) * 4;
    int n  = nt * 8 + (lane >> 2);
    float f = (k >= NI && k < NN - NO) ? REFRACTORY : 1.0f;
    float val = W[(size_t)k * NN + (NN - NO) + n] * f;
    g_Bpack[idx] = __uint_as_float(cvt_tf32(__float_as_uint(val)));
}

// ---------------- activation ----------------
__device__ __forceinline__ float activate(float x, int a) {
    if (a == 0) return fmaxf(x, 0.0f);
    if (a == 1) { float r; asm("tanh.approx.f32 %0, %1;" : "=f"(r) : "f"(x)); return r; }
    if (a == 2) {
        float e, r;
        asm("ex2.approx.f32 %0, %1;" : "=f"(e) : "f"(-1.4426950408889634f * x));
        asm("rcp.approx.f32 %0, %1;" : "=f"(r) : "f"(1.0f + e));
        return r;
    }
    return x;
}

// ---------------- main kernel ----------------
__global__ void __launch_bounds__(NTHREADS, 1)
nn_tf32_kernel(const float* __restrict__ prev,    // [B, N]
               const float* __restrict__ inp,     // [B, I]
               const float* __restrict__ biases,  // [N]
               const int*   __restrict__ act,     // [N]
               float* __restrict__ out)           // [B, O]
{
    extern __shared__ unsigned char smem[];
    const uint32_t sb = smem_u32(smem);
    const int tid  = threadIdx.x;
    const int lane = tid & 31;
    const int wid  = tid >> 5;          // 0..3: 32-row group
    const int row0 = blockIdx.x * MT;

    // issue A+B for chunk c into stage s (one commit group per call)
    auto issue = [&](int c, int s) {
        const uint32_t stage = sb + s * STAGE_BYTES;
        const float* src;
        int ldx;
        if (c < 2) { src = inp  + (size_t)row0 * NI + c * KC; ldx = NI; }
        else       { src = prev + (size_t)row0 * NN + c * KC; ldx = NN; }
#pragma unroll
        for (int i = 0; i < 16; ++i) {          // A: 32KB
            int g = tid + i * NTHREADS;         // 0..2047
            int row = g >> 4, u = g & 15;
            cp_async16(stage + a_off(row, u), src + (size_t)row * ldx + u * 4);
        }
        const float* bsrc = g_Bpack + (size_t)c * 4096;
#pragma unroll
        for (int i = 0; i < 8; ++i) {           // B: 16KB contiguous image
            int g = tid + i * NTHREADS;
            cp_async16(stage + A_BYTES + g * 16, bsrc + g * 4);
        }
    };

    // acc[mt][nt][4]: mt = 16-row half of this warp's 32 rows
    float acc[2][8][4];
#pragma unroll
    for (int mt = 0; mt < 2; ++mt)
#pragma unroll
        for (int nt = 0; nt < 8; ++nt)
#pragma unroll
            for (int i = 0; i < 4; ++i) acc[mt][nt][i] = 0.0f;

    // prologue
    issue(0, 0); CP_COMMIT();
    issue(1, 1); CP_COMMIT();

    const int r0w  = wid * 32 + (lane & 15);
    const int auhi = lane >> 4;

    for (int c = 0; c < NCHUNK; ++c) {
        const int s = c % STAGES;
        const uint32_t stage = sb + s * STAGE_BYTES;
        const uint32_t boff  = s * STAGE_BYTES + A_BYTES + lane * 16;

        CP_WAIT1();            // chunk c's group retired (c+1's may pend)
        __syncthreads();       // data visible; all warps done with c-1 -> stage (c+2)%3 free

        if (c + 2 < NCHUNK) issue(c + 2, (c + 2) % STAGES);
        CP_COMMIT();           // keep group accounting linear

        // B ks=0 prefetch from smem
        uint4 bq[4];
#pragma unroll
        for (int t = 0; t < 4; ++t)
            bq[t] = *(const uint4*)(smem + boff + t * 512);

#pragma unroll
        for (int ks = 0; ks < 8; ++ks) {
            uint4 bn[4];
            if (ks < 7) {
                uint32_t bnext = boff + (ks + 1) * 2048;
#pragma unroll
                for (int t = 0; t < 4; ++t)
                    bn[t] = *(const uint4*)(smem + bnext + t * 512);
            }
            uint32_t a0[4], a1[4];
            ldm_x4(a0, stage + a_off(r0w,      2 * ks + auhi));
            ldm_x4(a1, stage + a_off(r0w + 16, 2 * ks + auhi));
#pragma unroll
            for (int q = 0; q < 4; ++q) { a0[q] = cvt_tf32(a0[q]); a1[q] = cvt_tf32(a1[q]); }
#pragma unroll
            for (int ntp = 0; ntp < 4; ++ntp) {
                mma_tf32(acc[0][2 * ntp + 0], a0, bq[ntp].x, bq[ntp].y);
                mma_tf32(acc[0][2 * ntp + 1], a0, bq[ntp].z, bq[ntp].w);
                mma_tf32(acc[1][2 * ntp + 0], a1, bq[ntp].x, bq[ntp].y);
                mma_tf32(acc[1][2 * ntp + 1], a1, bq[ntp].z, bq[ntp].w);
            }
#pragma unroll
            for (int t = 0; t < 4; ++t) bq[t] = bn[t];
        }
    }

    // ---- epilogue: bias + heterogeneous activation + store ----
#pragma unroll
    for (int mt = 0; mt < 2; ++mt) {
        const int rg = row0 + wid * 32 + mt * 16 + (lane >> 2);
#pragma unroll
        for (int nt = 0; nt < 8; ++nt) {
            int col = nt * 8 + (lane & 3) * 2;
            float b0 = __ldg(biases + NN - NO + col);
            float b1 = __ldg(biases + NN - NO + col + 1);
            int   a0 = __ldg(act + NN - NO + col);
            int   a1 = __ldg(act + NN - NO + col + 1);
            float2 o;
            o.x = activate(acc[mt][nt][0] + b0, a0);
            o.y = activate(acc[mt][nt][1] + b1, a1);
            *(float2*)(out + (size_t)rg * NO + col) = o;
            o.x = activate(acc[mt][nt][2] + b0, a0);
            o.y = activate(acc[mt][nt][3] + b1, a1);
            *(float2*)(out + (size_t)(rg + 8) * NO + col) = o;
        }
    }
}

extern "C" void kernel_launch(void* const* d_in, const int* in_sizes, int n_in,
                              void* d_out, int out_size) {
    (void)in_sizes; (void)n_in; (void)out_size;
    const float* prev   = (const float*)d_in[0];  // [16384,1024]
    const float* inp    = (const float*)d_in[1];  // [16384,128]
    const float* W      = (const float*)d_in[2];  // [1024,1024]
    const float* biases = (const float*)d_in[3];  // [1024]
    const int*   act    = (const int*)d_in[4];    // [1024]
    float* out = (float*)d_out;                   // [16384,64]

    cudaFuncSetAttribute(nn_tf32_kernel, cudaFuncAttributeMaxDynamicSharedMemorySize, SMEM_TOTAL);

    prep_kernel<<<256, 256>>>(W);
    nn_tf32_kernel<<<GRID, NTHREADS, SMEM_TOTAL>>>(prev, inp, biases, act, out);
}

// round 17
// speedup vs baseline: 1.0883x; 1.0883x over previous
#include <cuda_runtime.h>
#include <cstdint>

// Problem constants
#define BATCH 16384
#define NN    1024
#define NI    128
#define NO    64
#define REFRACTORY 0.9f

#define KC       64
#define NCHUNK   (NN / KC)          // 16
#define MT       64                 // rows per CTA
#define NTHREADS 128                // 4 warps: 2 m-groups(32 rows) x 2 n-groups(32 cols)
#define GRID     (BATCH / MT)       // 256
#define STAGES   3

// ---- dynamic smem layout ----
// ring of 3 stages: A 16KB (64 rows x 256B, swizzled) + B 16KB (packed image)
#define A_BYTES     16384
#define B_BYTES     16384
#define STAGE_BYTES (A_BYTES + B_BYTES)          // 32768
#define SMEM_TOTAL  (STAGES * STAGE_BYTES)       // 98304

// B packed image (16KB per chunk), tf32-rounded, refractory-folded.
// Split by warpn so each warp's 32-col slice is contiguous:
// uint4 idx within chunk = ((warpn*8 + ks)*2 + ntp)*32 + lane ; 4 floats =
//   {nt=2ntp:k, nt=2ntp:k+4, nt=2ntp+1:k, nt=2ntp+1:k+4}
//   k = chunk*64 + ks*8 + (lane&3),  n = warpn*32 + nt*8 + (lane>>2)
__device__ __align__(16) float g_Bpack[NCHUNK * 2 * 8 * 2 * 32 * 4];

__device__ __forceinline__ uint32_t smem_u32(const void* p) {
    uint32_t a;
    asm("{ .reg .u64 t; cvta.to.shared.u64 t, %1; cvt.u32.u64 %0, t; }" : "=r"(a) : "l"(p));
    return a;
}
__device__ __forceinline__ void ldm_x4(uint32_t* r, uint32_t addr) {
    asm volatile("ldmatrix.sync.aligned.m8n8.x4.shared.b16 {%0,%1,%2,%3}, [%4];"
                 : "=r"(r[0]), "=r"(r[1]), "=r"(r[2]), "=r"(r[3]) : "r"(addr));
}
__device__ __forceinline__ void mma_tf32(float* d, const uint32_t* a, uint32_t b0, uint32_t b1) {
    asm volatile(
        "mma.sync.aligned.m16n8k8.row.col.f32.tf32.tf32.f32 "
        "{%0,%1,%2,%3}, {%4,%5,%6,%7}, {%8,%9}, {%0,%1,%2,%3};"
        : "+f"(d[0]), "+f"(d[1]), "+f"(d[2]), "+f"(d[3])
        : "r"(a[0]), "r"(a[1]), "r"(a[2]), "r"(a[3]), "r"(b0), "r"(b1));
}
__device__ __forceinline__ uint32_t cvt_tf32(uint32_t x) {
    uint32_t d;
    asm("cvt.rna.tf32.f32 %0, %1;" : "=r"(d) : "f"(__uint_as_float(x)));
    return d;
}
__device__ __forceinline__ void cp_async16(uint32_t smem_addr, const void* gptr) {
    asm volatile("cp.async.cg.shared.global [%0], [%1], 16;"
                 :: "r"(smem_addr), "l"(gptr) : "memory");
}
#define CP_COMMIT() asm volatile("cp.async.commit_group;" ::: "memory")
#define CP_WAIT1()  asm volatile("cp.async.wait_group 1;" ::: "memory")

// A stage: 64 rows x 16 units(16B); two 8KB halves (u<8 / u>=8), swizzled.
// Conflict-free for cp.async stores and ldmatrix reads.
__device__ __forceinline__ uint32_t a_off(int row, int u) {
    return (uint32_t)(((u >> 3) << 13) + (row << 7) + (((u & 7) ^ (row & 7)) << 4));
}

// ---------------- prep: round + fold + pack weight slice ----------------
__global__ void prep_kernel(const float* __restrict__ W) {
    int idx = blockIdx.x * blockDim.x + threadIdx.x;   // 0..65535
    if (idx >= NN * NO) return;
    int j     = idx & 3;
    int lane  = (idx >> 2) & 31;
    int ntp   = (idx >> 7) & 1;
    int ks    = (idx >> 8) & 7;
    int warpn = (idx >> 11) & 1;
    int chunk = idx >> 12;
    int nt = 2 * ntp + (j >> 1);
    int k  = chunk * 64 + ks * 8 + (lane & 3) + (j & 1) * 4;
    int n  = warpn * 32 + nt * 8 + (lane >> 2);
    float f = (k >= NI && k < NN - NO) ? REFRACTORY : 1.0f;
    float val = W[(size_t)k * NN + (NN - NO) + n] * f;
    g_Bpack[idx] = __uint_as_float(cvt_tf32(__float_as_uint(val)));
}

// ---------------- activation ----------------
__device__ __forceinline__ float activate(float x, int a) {
    if (a == 0) return fmaxf(x, 0.0f);
    if (a == 1) { float r; asm("tanh.approx.f32 %0, %1;" : "=f"(r) : "f"(x)); return r; }
    if (a == 2) {
        float e, r;
        asm("ex2.approx.f32 %0, %1;" : "=f"(e) : "f"(-1.4426950408889634f * x));
        asm("rcp.approx.f32 %0, %1;" : "=f"(r) : "f"(1.0f + e));
        return r;
    }
    return x;
}

// ---------------- main kernel ----------------
__global__ void __launch_bounds__(NTHREADS, 2)
nn_tf32_kernel(const float* __restrict__ prev,    // [B, N]
               const float* __restrict__ inp,     // [B, I]
               const float* __restrict__ biases,  // [N]
               const int*   __restrict__ act,     // [N]
               float* __restrict__ out)           // [B, O]
{
    extern __shared__ unsigned char smem[];
    const uint32_t sb = smem_u32(smem);
    const int tid   = threadIdx.x;
    const int lane  = tid & 31;
    const int wid   = tid >> 5;
    const int warpm = wid >> 1;     // 0..1: 32-row group
    const int warpn = wid & 1;      // 0..1: 32-col group
    const int row0  = blockIdx.x * MT;

    // issue A+B for chunk c into stage s (one commit group per call)
    auto issue = [&](int c, int s) {
        const uint32_t stage = sb + s * STAGE_BYTES;
        const float* src;
        int ldx;
        if (c < 2) { src = inp  + (size_t)row0 * NI + c * KC; ldx = NI; }
        else       { src = prev + (size_t)row0 * NN + c * KC; ldx = NN; }
#pragma unroll
        for (int i = 0; i < 8; ++i) {           // A: 16KB
            int g = tid + i * NTHREADS;         // 0..1023
            int row = g >> 4, u = g & 15;
            cp_async16(stage + a_off(row, u), src + (size_t)row * ldx + u * 4);
        }
        const float* bsrc = g_Bpack + (size_t)c * 4096;
#pragma unroll
        for (int i = 0; i < 8; ++i) {           // B: 16KB contiguous image
            int g = tid + i * NTHREADS;
            cp_async16(stage + A_BYTES + g * 16, bsrc + g * 4);
        }
    };

    // acc[mt][nt][4]: mt = 16-row half of the warp's 32 rows,
    //                 nt = 8-col tile of the warp's 32 cols
    float acc[2][4][4];
#pragma unroll
    for (int mt = 0; mt < 2; ++mt)
#pragma unroll
        for (int nt = 0; nt < 4; ++nt)
#pragma unroll
            for (int i = 0; i < 4; ++i) acc[mt][nt][i] = 0.0f;

    // prologue
    issue(0, 0); CP_COMMIT();
    issue(1, 1); CP_COMMIT();

    const int r0w  = warpm * 32 + (lane & 15);
    const int auhi = lane >> 4;

    for (int c = 0; c < NCHUNK; ++c) {
        const int s = c % STAGES;
        const uint32_t stage = sb + s * STAGE_BYTES;
        // warp's B slice: 8KB at A_BYTES + warpn*8192
        const uint32_t boff = s * STAGE_BYTES + A_BYTES + warpn * 8192 + lane * 16;

        CP_WAIT1();            // chunk c's group retired (c+1's may pend)
        __syncthreads();       // data visible; all warps done with c-1 -> stage (c+2)%3 free

        if (c + 2 < NCHUNK) issue(c + 2, (c + 2) % STAGES);
        CP_COMMIT();           // keep group accounting linear

        // B ks=0 prefetch from smem (2 x LDS.128, conflict-free)
        uint4 bq0 = *(const uint4*)(smem + boff);
        uint4 bq1 = *(const uint4*)(smem + boff + 512);

#pragma unroll
        for (int ks = 0; ks < 8; ++ks) {
            uint4 bn0, bn1;
            if (ks < 7) {
                bn0 = *(const uint4*)(smem + boff + (ks + 1) * 1024);
                bn1 = *(const uint4*)(smem + boff + (ks + 1) * 1024 + 512);
            }
            uint32_t a0[4], a1[4];
            ldm_x4(a0, stage + a_off(r0w,      2 * ks + auhi));
            ldm_x4(a1, stage + a_off(r0w + 16, 2 * ks + auhi));
#pragma unroll
            for (int q = 0; q < 4; ++q) { a0[q] = cvt_tf32(a0[q]); a1[q] = cvt_tf32(a1[q]); }

            mma_tf32(acc[0][0], a0, bq0.x, bq0.y);
            mma_tf32(acc[0][1], a0, bq0.z, bq0.w);
            mma_tf32(acc[0][2], a0, bq1.x, bq1.y);
            mma_tf32(acc[0][3], a0, bq1.z, bq1.w);
            mma_tf32(acc[1][0], a1, bq0.x, bq0.y);
            mma_tf32(acc[1][1], a1, bq0.z, bq0.w);
            mma_tf32(acc[1][2], a1, bq1.x, bq1.y);
            mma_tf32(acc[1][3], a1, bq1.z, bq1.w);

            bq0 = bn0; bq1 = bn1;
        }
    }

    // ---- epilogue: bias + heterogeneous activation + store ----
#pragma unroll
    for (int mt = 0; mt < 2; ++mt) {
        const int rg = row0 + warpm * 32 + mt * 16 + (lane >> 2);
#pragma unroll
        for (int nt = 0; nt < 4; ++nt) {
            int col = warpn * 32 + nt * 8 + (lane & 3) * 2;
            float b0 = __ldg(biases + NN - NO + col);
            float b1 = __ldg(biases + NN - NO + col + 1);
            int   a0 = __ldg(act + NN - NO + col);
            int   a1 = __ldg(act + NN - NO + col + 1);
            float2 o;
            o.x = activate(acc[mt][nt][0] + b0, a0);
            o.y = activate(acc[mt][nt][1] + b1, a1);
            *(float2*)(out + (size_t)rg * NO + col) = o;
            o.x = activate(acc[mt][nt][2] + b0, a0);
            o.y = activate(acc[mt][nt][3] + b1, a1);
            *(float2*)(out + (size_t)(rg + 8) * NO + col) = o;
        }
    }
}

extern "C" void kernel_launch(void* const* d_in, const int* in_sizes, int n_in,
                              void* d_out, int out_size) {
    (void)in_sizes; (void)n_in; (void)out_size;
    const float* prev   = (const float*)d_in[0];  // [16384,1024]
    const float* inp    = (const float*)d_in[1];  // [16384,128]
    const float* W      = (const float*)d_in[2];  // [1024,1024]
    const float* biases = (const float*)d_in[3];  // [1024]
    const int*   act    = (const int*)d_in[4];    // [1024]
    float* out = (float*)d_out;                   // [16384,64]

    cudaFuncSetAttribute(nn_tf32_kernel, cudaFuncAttributeMaxDynamicSharedMemorySize, SMEM_TOTAL);

    prep_kernel<<<256, 256>>>(W);
    nn_tf32_kernel<<<GRID, NTHREADS, SMEM_TOTAL>>>(prev, inp, biases, act, out);
}